// round 3
// baseline (speedup 1.0000x reference)
#include <cuda_runtime.h>
#include <float.h>

// SparseSoftmax: masked softmax over last axis of (32, 2048, 2048) fp32
// with int32 mask (mask = OD != 0). Fully-masked rows -> zeros.
//
// R3: persistent grid-stride kernel. Each CTA processes ~54 rows and
// software-pipelines: next row's loads are issued before the current row's
// reductions/exp/store, so DRAM requests stay in flight across the barrier
// phases and across row boundaries (no CTA-exit bubbles).

#define ROW_LEN 2048
#define THREADS 256
#define NWARPS  (THREADS / 32)

__global__ __launch_bounds__(THREADS)
void sparse_softmax_kernel(const float* __restrict__ f,
                           const int* __restrict__ od,
                           float* __restrict__ out,
                           int rows)
{
    const int t    = threadIdx.x;
    const int warp = t >> 5;
    const int lane = t & 31;
    const int stride = gridDim.x;

    __shared__ float smax[NWARPS];
    __shared__ float ssum[NWARPS];

    int row = blockIdx.x;
    if (row >= rows) return;

    // --- prologue: load first row ---
    size_t base = (size_t)row * ROW_LEN;
    float4 v0 = __ldcs((const float4*)(f  + base) + t);
    float4 v1 = __ldcs((const float4*)(f  + base) + t + THREADS);
    int4   m0 = __ldcs((const int4*)  (od + base) + t);
    int4   m1 = __ldcs((const int4*)  (od + base) + t + THREADS);

    while (true) {
        const int next = row + stride;
        const bool has_next = next < rows;

        // --- prefetch next row (in flight during reductions below) ---
        float4 nv0, nv1; int4 nm0, nm1;
        if (has_next) {
            size_t nbase = (size_t)next * ROW_LEN;
            nv0 = __ldcs((const float4*)(f  + nbase) + t);
            nv1 = __ldcs((const float4*)(f  + nbase) + t + THREADS);
            nm0 = __ldcs((const int4*)  (od + nbase) + t);
            nm1 = __ldcs((const int4*)  (od + nbase) + t + THREADS);
        }

        float vals[8] = {v0.x, v0.y, v0.z, v0.w, v1.x, v1.y, v1.z, v1.w};
        int   msk [8] = {m0.x, m0.y, m0.z, m0.w, m1.x, m1.y, m1.z, m1.w};

        // --- local + warp max over unmasked lanes ---
        float mx = -FLT_MAX;
        #pragma unroll
        for (int i = 0; i < 8; i++)
            if (msk[i] != 0) mx = fmaxf(mx, vals[i]);
        #pragma unroll
        for (int o = 16; o > 0; o >>= 1)
            mx = fmaxf(mx, __shfl_xor_sync(0xffffffffu, mx, o));
        if (lane == 0) smax[warp] = mx;
        __syncthreads();

        float rowmax = smax[0];
        #pragma unroll
        for (int w = 1; w < NWARPS; w++) rowmax = fmaxf(rowmax, smax[w]);

        // --- exp + sum (exp only on unmasked lanes) ---
        float p[8];
        float sum = 0.0f;
        #pragma unroll
        for (int i = 0; i < 8; i++) {
            float e = (msk[i] != 0) ? __expf(vals[i] - rowmax) : 0.0f;
            p[i] = e;
            sum += e;
        }
        #pragma unroll
        for (int o = 16; o > 0; o >>= 1)
            sum += __shfl_xor_sync(0xffffffffu, sum, o);
        if (lane == 0) ssum[warp] = sum;
        __syncthreads();

        float s = ssum[0];
        #pragma unroll
        for (int w = 1; w < NWARPS; w++) s += ssum[w];
        const float inv = (s > 0.0f) ? (1.0f / s) : 0.0f;  // fully-masked -> zeros

        // --- normalize + streaming write ---
        float4 r0 = make_float4(p[0] * inv, p[1] * inv, p[2] * inv, p[3] * inv);
        float4 r1 = make_float4(p[4] * inv, p[5] * inv, p[6] * inv, p[7] * inv);
        float4* out4 = (float4*)(out + base);
        __stcs(&out4[t],           r0);
        __stcs(&out4[t + THREADS], r1);

        if (!has_next) break;
        row = next;
        base = (size_t)row * ROW_LEN;
        v0 = nv0; v1 = nv1; m0 = nm0; m1 = nm1;
    }
}

extern "C" void kernel_launch(void* const* d_in, const int* in_sizes, int n_in,
                              void* d_out, int out_size)
{
    const float* features = (const float*)d_in[0];
    const int*   OD       = (const int*)d_in[1];
    float*       out      = (float*)d_out;

    const int rows = in_sizes[0] / ROW_LEN;   // 32*2048 = 65536

    // Persistent grid: 8 CTAs per SM (152 SMs on GB300).
    int grid = 152 * 8;
    if (grid > rows) grid = rows;
    sparse_softmax_kernel<<<grid, THREADS>>>(features, OD, out, rows);
}